// round 12
// baseline (speedup 1.0000x reference)
#include <cuda_runtime.h>
#include <cstdint>

#define N_NODES 100000
#define N_EDGES 1600000
#define N_GRAPHS 256
#define IN_C 64
#define HID 128
#define BN_EPS 1e-5f
#define CK 32                    // weight k-chunk
#define SWS 136                  // weight chunk row stride (floats) -> B frag conflict-free
#define REGION_FL (128 * 132)    // z tile then hidden tile overlay
#define SW_FL (CK * SWS)         // one weight buffer (4352 floats)
#define SCAN_BLKS ((N_NODES + 255) / 256)   // 391

// ---- tf32 helpers ----
__device__ __forceinline__ uint32_t f2tf(float f) {
    uint32_t u; asm("cvt.rna.tf32.f32 %0, %1;" : "=r"(u) : "f"(f)); return u;
}
__device__ __forceinline__ void mma_tf32(float (&d)[4], const uint32_t (&a)[4],
                                         uint32_t b0, uint32_t b1) {
    asm volatile(
        "mma.sync.aligned.m16n8k8.row.col.f32.tf32.tf32.f32 "
        "{%0,%1,%2,%3},{%4,%5,%6,%7},{%8,%9},{%0,%1,%2,%3};"
        : "+f"(d[0]), "+f"(d[1]), "+f"(d[2]), "+f"(d[3])
        : "r"(a[0]), "r"(a[1]), "r"(a[2]), "r"(a[3]), "r"(b0), "r"(b1));
}

// ---- cp.async helpers ----
__device__ __forceinline__ uint32_t smem_u32(const void* p) {
    uint32_t a;
    asm("{ .reg .u64 t; cvta.to.shared.u64 t, %1; cvt.u32.u64 %0, t; }" : "=r"(a) : "l"(p));
    return a;
}
__device__ __forceinline__ void cpasync16(uint32_t saddr, const void* gptr) {
    asm volatile("cp.async.ca.shared.global [%0], [%1], 16;" :: "r"(saddr), "l"(gptr));
}
#define CP_COMMIT() asm volatile("cp.async.commit_group;" ::: "memory")
#define CP_WAIT0()  asm volatile("cp.async.wait_group 0;" ::: "memory")

// ---------------- scratch (device globals; no allocation) ----------------
__device__ float g_Z0[(size_t)N_NODES * HID];
__device__ float g_Z1[(size_t)N_NODES * HID];
__device__ float g_AGG[(size_t)N_NODES * HID];
__device__ float g_STATS[2 * HID];
__device__ float g_SCALE[3 * HID];
__device__ float g_SHIFT[3 * HID];
__device__ float g_POOL[N_GRAPHS * HID];
__device__ float g_CINV[N_GRAPHS];
__device__ int   g_DEG[N_NODES];
__device__ int   g_OFFS[N_NODES];
__device__ int   g_CURS[N_NODES];
__device__ int   g_BSUM[SCAN_BLKS];
__device__ int   g_CSR[N_EDGES];
__device__ uint32_t g_WTF[22 * SW_FL];   // pre-converted tf32 weights, smem chunk layout

// ---------------- small utility kernels ----------------
__global__ void zero_kernel(float* p, int n) {
    int i = blockIdx.x * blockDim.x + threadIdx.x;
    if (i < n) p[i] = 0.f;
}
__global__ void zeroi_kernel(int* p, int n) {
    int i = blockIdx.x * blockDim.x + threadIdx.x;
    if (i < n) p[i] = 0;
}

// ---- one-shot weight pre-convert: fp32 [K,HID] -> tf32 bits, chunked/padded ----
__global__ void wconv_kernel(const float* __restrict__ src, uint32_t* __restrict__ dst, int K) {
    int i = blockIdx.x * 256 + threadIdx.x;
    if (i >= K * HID) return;
    int k = i / HID, c = i % HID;
    dst[(k / CK) * SW_FL + (k % CK) * SWS + c] = f2tf(src[i]);
}

// ================= CSR build =================
__global__ void hist_kernel(const int* __restrict__ ei, int* __restrict__ deg) {
    int e = blockIdx.x * blockDim.x + threadIdx.x;
    if (e < N_EDGES) atomicAdd(&deg[ei[N_EDGES + e]], 1);
}

__global__ void scan_block_kernel(const int* __restrict__ deg,
                                  int* __restrict__ offs, int* __restrict__ bsum) {
    __shared__ int s[256];
    int tid = threadIdx.x;
    int i = blockIdx.x * 256 + tid;
    int v = (i < N_NODES) ? deg[i] : 0;
    s[tid] = v;
    __syncthreads();
    #pragma unroll
    for (int d = 1; d < 256; d <<= 1) {
        int t = (tid >= d) ? s[tid - d] : 0;
        __syncthreads();
        s[tid] += t;
        __syncthreads();
    }
    if (i < N_NODES) offs[i] = s[tid] - v;
    if (tid == 255) bsum[blockIdx.x] = s[255];
}

__global__ void scan_bsum_kernel(int* __restrict__ bsum) {
    __shared__ int s[512];
    int tid = threadIdx.x;
    int v = (tid < SCAN_BLKS) ? bsum[tid] : 0;
    s[tid] = v;
    __syncthreads();
    #pragma unroll
    for (int d = 1; d < 512; d <<= 1) {
        int t = (tid >= d) ? s[tid - d] : 0;
        __syncthreads();
        s[tid] += t;
        __syncthreads();
    }
    if (tid < SCAN_BLKS) bsum[tid] = s[tid] - v;
}

__global__ void scan_add_kernel(int* __restrict__ offs, const int* __restrict__ bsum,
                                int* __restrict__ curs) {
    int i = blockIdx.x * 256 + threadIdx.x;
    if (i < N_NODES) {
        int o = offs[i] + bsum[blockIdx.x];
        offs[i] = o;
        curs[i] = o;
    }
}

__global__ void fill_kernel(const int* __restrict__ ei, int* __restrict__ curs,
                            int* __restrict__ csr) {
    int e = blockIdx.x * blockDim.x + threadIdx.x;
    if (e < N_EDGES) {
        int d = ei[N_EDGES + e];
        int slot = atomicAdd(&curs[d], 1);
        csr[slot] = ei[e];
    }
}

// ================= gather-aggregate (atomic-free, BN fused) =================
__global__ __launch_bounds__(256)
void gather64_kernel(const int* __restrict__ deg, const int* __restrict__ offs,
                     const int* __restrict__ csr, const float* __restrict__ z,
                     float* __restrict__ outz) {
    int node = (blockIdx.x * 256 + threadIdx.x) >> 5;
    if (node >= N_NODES) return;
    int lane = threadIdx.x & 31;
    int c = lane * 2;
    float2 acc = *(const float2*)(z + (size_t)node * IN_C + c);
    int beg = offs[node], n = deg[node];
    int e = 0;
    for (; e + 2 <= n; e += 2) {
        int s0 = csr[beg + e], s1 = csr[beg + e + 1];
        float2 v0 = *(const float2*)(z + (size_t)s0 * IN_C + c);
        float2 v1 = *(const float2*)(z + (size_t)s1 * IN_C + c);
        acc.x += v0.x + v1.x;
        acc.y += v0.y + v1.y;
    }
    if (e < n) {
        int s0 = csr[beg + e];
        float2 v0 = *(const float2*)(z + (size_t)s0 * IN_C + c);
        acc.x += v0.x; acc.y += v0.y;
    }
    *(float2*)(outz + (size_t)node * IN_C + c) = acc;
}

__global__ __launch_bounds__(256)
void gather128_kernel(const int* __restrict__ deg, const int* __restrict__ offs,
                      const int* __restrict__ csr, const float* __restrict__ z,
                      const float* __restrict__ scale, const float* __restrict__ shift,
                      float* __restrict__ outz) {
    int node = (blockIdx.x * 256 + threadIdx.x) >> 5;
    if (node >= N_NODES) return;
    int lane = threadIdx.x & 31;
    int c = lane * 4;
    float4 sc = *(const float4*)(scale + c);
    float4 sh = *(const float4*)(shift + c);

    float4 v = *(const float4*)(z + (size_t)node * HID + c);
    float4 acc;
    acc.x = fmaxf(fmaf(v.x, sc.x, sh.x), 0.f);
    acc.y = fmaxf(fmaf(v.y, sc.y, sh.y), 0.f);
    acc.z = fmaxf(fmaf(v.z, sc.z, sh.z), 0.f);
    acc.w = fmaxf(fmaf(v.w, sc.w, sh.w), 0.f);

    int beg = offs[node], n = deg[node];
    int e = 0;
    for (; e + 2 <= n; e += 2) {
        int s0 = csr[beg + e], s1 = csr[beg + e + 1];
        float4 v0 = *(const float4*)(z + (size_t)s0 * HID + c);
        float4 v1 = *(const float4*)(z + (size_t)s1 * HID + c);
        acc.x += fmaxf(fmaf(v0.x, sc.x, sh.x), 0.f) + fmaxf(fmaf(v1.x, sc.x, sh.x), 0.f);
        acc.y += fmaxf(fmaf(v0.y, sc.y, sh.y), 0.f) + fmaxf(fmaf(v1.y, sc.y, sh.y), 0.f);
        acc.z += fmaxf(fmaf(v0.z, sc.z, sh.z), 0.f) + fmaxf(fmaf(v1.z, sc.z, sh.z), 0.f);
        acc.w += fmaxf(fmaf(v0.w, sc.w, sh.w), 0.f) + fmaxf(fmaf(v1.w, sc.w, sh.w), 0.f);
    }
    if (e < n) {
        int s0 = csr[beg + e];
        float4 v0 = *(const float4*)(z + (size_t)s0 * HID + c);
        acc.x += fmaxf(fmaf(v0.x, sc.x, sh.x), 0.f);
        acc.y += fmaxf(fmaf(v0.y, sc.y, sh.y), 0.f);
        acc.z += fmaxf(fmaf(v0.z, sc.z, sh.z), 0.f);
        acc.w += fmaxf(fmaf(v0.w, sc.w, sh.w), 0.f);
    }
    *(float4*)(outz + (size_t)node * HID + c) = acc;
}

// ---------------- fused MLP (tf32 mma.sync, pre-converted weights via cp.async) ----------------
// 128x128 tile / block, 256 threads = 8 warps; warp tile 32(m) x 64(n).
// Weight chunks already tf32 bits in SWS-padded chunk layout -> raw cp.async double buffer.
template <int CIN>
__global__ __launch_bounds__(256, 2)
void mlp_kernel(const float* __restrict__ zin,
                const uint32_t* __restrict__ w1tf, const float* __restrict__ b1,
                const uint32_t* __restrict__ w2tf, const float* __restrict__ b2,
                float* __restrict__ zout, float* __restrict__ stats) {
    extern __shared__ float sm[];
    float* region = sm;                     // REGION_FL (z tile, then hidden tile)
    float* swbuf  = sm + REGION_FL;         // 2 * SW_FL (tf32 weight chunks)
    float* ssum   = swbuf + 2 * SW_FL;      // HID
    float* ssq    = ssum + HID;             // HID

    const int SZS = CIN + 4;                // z row stride (A frags conflict-free)
    const int tid  = threadIdx.x;
    const int row0 = blockIdx.x * 128;
    const int lane = tid & 31;
    const int wid  = tid >> 5;
    const int g    = lane >> 2;             // groupID (0..7)
    const int tig  = lane & 3;              // thread-in-group (0..3)
    const int wm   = (wid & 3) * 32;        // warp m base
    const int n0   = (wid >> 2) * 64;       // warp n base

    const uint32_t sw_addr = smem_u32(swbuf);
    const int NKC = CIN / CK;
    const int NKC2 = HID / CK;

    if (tid < HID) { ssum[tid] = 0.f; ssq[tid] = 0.f; }

    // ---- prefetch w1 chunk 0 into buffer 0 (raw cp.async) ----
    {
        const uint4* src = (const uint4*)w1tf;
        for (int i = tid; i < SW_FL / 4; i += 256) cpasync16(sw_addr + i * 16, src + i);
        CP_COMMIT();
    }

    // ---- stage z tile as tf32 bits (LDG overlaps the cp.async) ----
    {
        const int QPR = CIN / 4;
        #pragma unroll
        for (int t = 0; t < (128 * QPR) / 256; t++) {
            int i = t * 256 + tid;
            int r = i / QPR, q = i % QPR;
            int gr = row0 + r;
            float4 v = make_float4(0.f, 0.f, 0.f, 0.f);
            if (gr < N_NODES)
                v = *(const float4*)(zin + (size_t)gr * CIN + q * 4);
            uint4 u = make_uint4(f2tf(v.x), f2tf(v.y), f2tf(v.z), f2tf(v.w));
            *(uint4*)&region[r * SZS + q * 4] = u;
        }
    }
    CP_WAIT0();
    __syncthreads();

    float acc[2][8][4];

    // ======== GEMM1: hidden = relu(z @ w1 + b1) ========
    {
        #pragma unroll
        for (int mt = 0; mt < 2; mt++)
            #pragma unroll
            for (int j = 0; j < 8; j++) {
                int c = n0 + j * 8 + 2 * tig;
                acc[mt][j][0] = b1[c]; acc[mt][j][1] = b1[c + 1];
                acc[mt][j][2] = b1[c]; acc[mt][j][3] = b1[c + 1];
            }

        for (int kc = 0; kc < NKC; kc++) {
            // prefetch next chunk (w1 tail, then w2 chunk 0) into other buffer
            {
                const uint4* src = (kc + 1 < NKC)
                    ? (const uint4*)(w1tf + (size_t)(kc + 1) * SW_FL)
                    : (const uint4*)w2tf;
                uint32_t dst = sw_addr + ((kc + 1) & 1) * (SW_FL * 4);
                for (int i = tid; i < SW_FL / 4; i += 256) cpasync16(dst + i * 16, src + i);
                CP_COMMIT();
            }
            const uint32_t* zr = (const uint32_t*)region;
            const uint32_t* wr = (const uint32_t*)(swbuf + (kc & 1) * SW_FL);
            #pragma unroll
            for (int ks = 0; ks < CK / 8; ks++) {
                int kb = ks * 8;
                int kg = kc * CK + kb + tig;
                uint32_t a[2][4];
                #pragma unroll
                for (int mt = 0; mt < 2; mt++) {
                    int rb = wm + mt * 16 + g;
                    a[mt][0] = zr[rb * SZS + kg];
                    a[mt][1] = zr[(rb + 8) * SZS + kg];
                    a[mt][2] = zr[rb * SZS + kg + 4];
                    a[mt][3] = zr[(rb + 8) * SZS + kg + 4];
                }
                #pragma unroll
                for (int j = 0; j < 8; j++) {
                    int cB = n0 + j * 8 + g;
                    uint32_t b0 = wr[(kb + tig) * SWS + cB];
                    uint32_t bq = wr[(kb + tig + 4) * SWS + cB];
                    mma_tf32(acc[0][j], a[0], b0, bq);
                    mma_tf32(acc[1][j], a[1], b0, bq);
                }
            }
            CP_WAIT0();
            __syncthreads();   // prefetched chunk visible; readers of current chunk + z done
        }

        // relu + cvt -> store hidden (tf32 bits) at stride 132 (z lifetime over)
        #pragma unroll
        for (int mt = 0; mt < 2; mt++)
            #pragma unroll
            for (int half = 0; half < 2; half++) {
                int row = wm + mt * 16 + half * 8 + g;
                #pragma unroll
                for (int j = 0; j < 8; j++) {
                    int c = n0 + j * 8 + 2 * tig;
                    uint2 u = make_uint2(
                        f2tf(fmaxf(acc[mt][j][half * 2 + 0], 0.f)),
                        f2tf(fmaxf(acc[mt][j][half * 2 + 1], 0.f)));
                    *(uint2*)&region[row * 132 + c] = u;
                }
            }
        __syncthreads();
    }

    // ======== GEMM2: out = hidden @ w2 + b2 ========
    {
        #pragma unroll
        for (int mt = 0; mt < 2; mt++)
            #pragma unroll
            for (int j = 0; j < 8; j++) {
                int c = n0 + j * 8 + 2 * tig;
                acc[mt][j][0] = b2[c]; acc[mt][j][1] = b2[c + 1];
                acc[mt][j][2] = b2[c]; acc[mt][j][3] = b2[c + 1];
            }

        for (int kc = 0; kc < NKC2; kc++) {
            if (kc + 1 < NKC2) {
                const uint4* src = (const uint4*)(w2tf + (size_t)(kc + 1) * SW_FL);
                uint32_t dst = sw_addr + ((NKC + kc + 1) & 1) * (SW_FL * 4);
                for (int i = tid; i < SW_FL / 4; i += 256) cpasync16(dst + i * 16, src + i);
                CP_COMMIT();
            }
            const uint32_t* hr = (const uint32_t*)region;
            const uint32_t* wr = (const uint32_t*)(swbuf + ((NKC + kc) & 1) * SW_FL);
            #pragma unroll
            for (int ks = 0; ks < CK / 8; ks++) {
                int kb = ks * 8;
                int kg = kc * CK + kb + tig;
                uint32_t a[2][4];
                #pragma unroll
                for (int mt = 0; mt < 2; mt++) {
                    int rb = wm + mt * 16 + g;
                    a[mt][0] = hr[rb * 132 + kg];
                    a[mt][1] = hr[(rb + 8) * 132 + kg];
                    a[mt][2] = hr[rb * 132 + kg + 4];
                    a[mt][3] = hr[(rb + 8) * 132 + kg + 4];
                }
                #pragma unroll
                for (int j = 0; j < 8; j++) {
                    int cB = n0 + j * 8 + g;
                    uint32_t b0 = wr[(kb + tig) * SWS + cB];
                    uint32_t bq = wr[(kb + tig + 4) * SWS + cB];
                    mma_tf32(acc[0][j], a[0], b0, bq);
                    mma_tf32(acc[1][j], a[1], b0, bq);
                }
            }
            if (kc + 1 < NKC2) {
                CP_WAIT0();
                __syncthreads();
            }
        }
    }

    // ======== epilogue: store pre-BN z, accumulate BN column stats ========
    float s[16], q[16];
    #pragma unroll
    for (int j = 0; j < 16; j++) { s[j] = 0.f; q[j] = 0.f; }

    #pragma unroll
    for (int mt = 0; mt < 2; mt++)
        #pragma unroll
        for (int half = 0; half < 2; half++) {
            int gr = row0 + wm + mt * 16 + half * 8 + g;
            if (gr < N_NODES) {
                #pragma unroll
                for (int j = 0; j < 8; j++) {
                    float v0 = acc[mt][j][half * 2 + 0];
                    float v1 = acc[mt][j][half * 2 + 1];
                    int c = n0 + j * 8 + 2 * tig;
                    *(float2*)&zout[(size_t)gr * HID + c] = make_float2(v0, v1);
                    s[2 * j] += v0;     q[2 * j] += v0 * v0;
                    s[2 * j + 1] += v1; q[2 * j + 1] += v1 * v1;
                }
            }
        }
    #pragma unroll
    for (int j = 0; j < 8; j++) {
        int c = n0 + j * 8 + 2 * tig;
        atomicAdd(&ssum[c], s[2 * j]);
        atomicAdd(&ssq[c], q[2 * j]);
        atomicAdd(&ssum[c + 1], s[2 * j + 1]);
        atomicAdd(&ssq[c + 1], q[2 * j + 1]);
    }
    __syncthreads();
    if (tid < HID) {
        atomicAdd(&stats[tid], ssum[tid]);
        atomicAdd(&stats[HID + tid], ssq[tid]);
    }
}

// ---------------- BN finalize ----------------
__global__ void bn_finalize_kernel(const float* __restrict__ gamma,
                                   const float* __restrict__ beta,
                                   const float* __restrict__ stats,
                                   float* __restrict__ scale,
                                   float* __restrict__ shift) {
    int c = threadIdx.x;
    float mean = stats[c] * (1.f / N_NODES);
    float var  = stats[HID + c] * (1.f / N_NODES) - mean * mean;
    float inv  = rsqrtf(var + BN_EPS);
    float sc   = gamma[c] * inv;
    scale[c] = sc;
    shift[c] = beta[c] - mean * sc;
}

// ---------------- mean pool with fused BN+relu (batch sorted) ----------------
__global__ void pool_kernel(const float* __restrict__ z, const int* __restrict__ batch,
                            const float* __restrict__ scale, const float* __restrict__ shift,
                            float* __restrict__ pool) {
    __shared__ int sb[256];
    int r0  = blockIdx.x * 256;
    int tid = threadIdx.x;  // 128 threads, one column each
    for (int i = tid; i < 256; i += 128) {
        int gr = r0 + i;
        sb[i] = (gr < N_NODES) ? batch[gr] : -1;
    }
    __syncthreads();
    int c = tid;
    float sc = scale[c], sh = shift[c];
    float sum = 0.f;
    int cur = sb[0];
    for (int i = 0; i < 256; i++) {
        int gr = r0 + i;
        if (gr >= N_NODES) break;
        int b = sb[i];
        if (b != cur) {
            atomicAdd(&pool[cur * HID + c], sum);
            sum = 0.f; cur = b;
        }
        sum += fmaxf(fmaf(z[(long long)gr * HID + c], sc, sh), 0.f);
    }
    if (cur >= 0) atomicAdd(&pool[cur * HID + c], sum);
}

// ---------------- per-graph counts via binary search ----------------
__global__ void count_kernel(const int* __restrict__ batch, float* __restrict__ cinv) {
    int g = threadIdx.x;
    int lo = 0, hi = N_NODES;
    while (lo < hi) { int m = (lo + hi) >> 1; if (batch[m] < g) lo = m + 1; else hi = m; }
    int a = lo;
    lo = 0; hi = N_NODES;
    while (lo < hi) { int m = (lo + hi) >> 1; if (batch[m] < g + 1) lo = m + 1; else hi = m; }
    float cnt = (float)(lo - a);
    cinv[g] = 1.f / fmaxf(cnt, 1.f);
}

// ---------------- final projection ----------------
__global__ void proj_kernel(const float* __restrict__ w, const float* __restrict__ b,
                            const float* __restrict__ pool, const float* __restrict__ cinv,
                            float* __restrict__ out) {
    __shared__ float hg[HID];
    int g = blockIdx.x, t = threadIdx.x;
    hg[t] = pool[g * HID + t] * cinv[g];
    __syncthreads();
    float acc = b[t];
    #pragma unroll 8
    for (int k = 0; k < HID; k++) acc = fmaf(hg[k], w[k * HID + t], acc);
    out[g * HID + t] = acc;
}

// ---------------- host orchestration ----------------
static void* sym(const void* s) {
    void* p = nullptr;
    cudaGetSymbolAddress(&p, s);
    return p;
}

extern "C" void kernel_launch(void* const* d_in, const int* in_sizes, int n_in,
                              void* d_out, int out_size) {
    const float* x     = (const float*)d_in[0];
    const int*   ei    = (const int*)d_in[1];
    const int*   batch = (const int*)d_in[2];
    const float* L[3][6];
    for (int l = 0; l < 3; l++)
        for (int k = 0; k < 6; k++) L[l][k] = (const float*)d_in[3 + 6 * l + k];
    const float* proj_w = (const float*)d_in[21];
    const float* proj_b = (const float*)d_in[22];
    float* out = (float*)d_out;

    float* Z0    = (float*)sym(g_Z0);
    float* Z1    = (float*)sym(g_Z1);
    float* AGG   = (float*)sym(g_AGG);
    float* STATS = (float*)sym(g_STATS);
    float* SCALE = (float*)sym(g_SCALE);
    float* SHIFT = (float*)sym(g_SHIFT);
    float* POOL  = (float*)sym(g_POOL);
    float* CINV  = (float*)sym(g_CINV);
    int*   DEG   = (int*)sym(g_DEG);
    int*   OFFS  = (int*)sym(g_OFFS);
    int*   CURS  = (int*)sym(g_CURS);
    int*   BSUM  = (int*)sym(g_BSUM);
    int*   CSR   = (int*)sym(g_CSR);
    uint32_t* WTF = (uint32_t*)sym(g_WTF);

    // chunk offsets within WTF: l0.w1(2) l0.w2(4) l1.w1(4) l1.w2(4) l2.w1(4) l2.w2(4)
    uint32_t* W1TF[3] = { WTF,              WTF + 6 * SW_FL,  WTF + 14 * SW_FL };
    uint32_t* W2TF[3] = { WTF + 2 * SW_FL,  WTF + 10 * SW_FL, WTF + 18 * SW_FL };

    const int smemMlp = (REGION_FL + 2 * SW_FL + 2 * HID) * 4;   // ~103 KB -> 2 CTAs/SM
    cudaFuncSetAttribute(mlp_kernel<IN_C>, cudaFuncAttributeMaxDynamicSharedMemorySize, smemMlp);
    cudaFuncSetAttribute(mlp_kernel<HID>,  cudaFuncAttributeMaxDynamicSharedMemorySize, smemMlp);

    const int mlpBlocks  = (N_NODES + 127) / 128;
    const int edgeBlocks = (N_EDGES + 255) / 256;
    const int gathBlocks = (N_NODES * 32 + 255) / 256;   // warp per node

    // ---- one-shot weight pre-conversion ----
    wconv_kernel<<<(IN_C * HID + 255) / 256, 256>>>(L[0][0], W1TF[0], IN_C);
    wconv_kernel<<<(HID * HID + 255) / 256, 256>>>(L[0][2], W2TF[0], HID);
    for (int l = 1; l < 3; l++) {
        wconv_kernel<<<(HID * HID + 255) / 256, 256>>>(L[l][0], W1TF[l], HID);
        wconv_kernel<<<(HID * HID + 255) / 256, 256>>>(L[l][2], W2TF[l], HID);
    }

    // ---- CSR build (reused by all 3 layers) ----
    zeroi_kernel<<<SCAN_BLKS, 256>>>(DEG, N_NODES);
    hist_kernel<<<edgeBlocks, 256>>>(ei, DEG);
    scan_block_kernel<<<SCAN_BLKS, 256>>>(DEG, OFFS, BSUM);
    scan_bsum_kernel<<<1, 512>>>(BSUM);
    scan_add_kernel<<<SCAN_BLKS, 256>>>(OFFS, BSUM, CURS);
    fill_kernel<<<edgeBlocks, 256>>>(ei, CURS, CSR);

    // ---- layer 0 (CIN=64): z_in = x + sum_N x ----
    gather64_kernel<<<gathBlocks, 256>>>(DEG, OFFS, CSR, x, AGG);
    zero_kernel<<<1, 256>>>(STATS, 2 * HID);
    mlp_kernel<IN_C><<<mlpBlocks, 256, smemMlp>>>(
        AGG, W1TF[0], L[0][1], W2TF[0], L[0][3], Z0, STATS);
    bn_finalize_kernel<<<1, HID>>>(L[0][4], L[0][5], STATS, SCALE, SHIFT);

    // ---- layers 1,2 (CIN=128), BN of previous layer fused into gather ----
    const float* zprev = Z0;
    float* zcur = Z1;
    for (int l = 1; l < 3; l++) {
        const float* sc = SCALE + (l - 1) * HID;
        const float* sh = SHIFT + (l - 1) * HID;
        gather128_kernel<<<gathBlocks, 256>>>(DEG, OFFS, CSR, zprev, sc, sh, AGG);
        zero_kernel<<<1, 256>>>(STATS, 2 * HID);
        mlp_kernel<HID><<<mlpBlocks, 256, smemMlp>>>(
            AGG, W1TF[l], L[l][1], W2TF[l], L[l][3], zcur, STATS);
        bn_finalize_kernel<<<1, HID>>>(L[l][4], L[l][5], STATS, SCALE + l * HID, SHIFT + l * HID);
        const float* t = zprev; zprev = zcur; zcur = (float*)t;
    }

    // ---- pool + projection (BN of layer 2 fused into pool) ----
    zero_kernel<<<(N_GRAPHS * HID + 255) / 256, 256>>>(POOL, N_GRAPHS * HID);
    pool_kernel<<<(N_NODES + 255) / 256, 128>>>(zprev, batch, SCALE + 2 * HID, SHIFT + 2 * HID, POOL);
    count_kernel<<<1, N_GRAPHS>>>(batch, CINV);
    proj_kernel<<<N_GRAPHS, HID>>>(proj_w, proj_b, POOL, CINV, out);
}

// round 16
// speedup vs baseline: 1.0407x; 1.0407x over previous
#include <cuda_runtime.h>
#include <cstdint>

#define N_NODES 100000
#define N_EDGES 1600000
#define N_GRAPHS 256
#define IN_C 64
#define HID 128
#define BN_EPS 1e-5f
#define CK 32                    // weight k-chunk
#define SWS 136                  // weight chunk row stride (floats) -> B frag conflict-free
#define REGION_FL (128 * 132)    // z tile then hidden tile overlay
#define SW_FL (CK * SWS)         // one weight buffer
#define SCAN_BLKS ((N_NODES + 255) / 256)   // 391

// ---- tf32 helpers ----
__device__ __forceinline__ uint32_t f2tf(float f) {
    uint32_t u; asm("cvt.rna.tf32.f32 %0, %1;" : "=r"(u) : "f"(f)); return u;
}
__device__ __forceinline__ void mma_tf32(float (&d)[4], const uint32_t (&a)[4],
                                         uint32_t b0, uint32_t b1) {
    asm volatile(
        "mma.sync.aligned.m16n8k8.row.col.f32.tf32.tf32.f32 "
        "{%0,%1,%2,%3},{%4,%5,%6,%7},{%8,%9},{%0,%1,%2,%3};"
        : "+f"(d[0]), "+f"(d[1]), "+f"(d[2]), "+f"(d[3])
        : "r"(a[0]), "r"(a[1]), "r"(a[2]), "r"(a[3]), "r"(b0), "r"(b1));
}

// ---------------- scratch (device globals; no allocation) ----------------
__device__ float g_Z0[(size_t)N_NODES * HID];
__device__ float g_Z1[(size_t)N_NODES * HID];
__device__ float g_AGG[(size_t)N_NODES * HID];
__device__ float g_STATS[3 * 2 * HID];
__device__ float g_SCALE[3 * HID];
__device__ float g_SHIFT[3 * HID];
__device__ float g_POOL[N_GRAPHS * HID];
__device__ float g_CINV[N_GRAPHS];
__device__ int   g_DEG[N_NODES];
__device__ int   g_OFFS[N_NODES];
__device__ int   g_CURS[N_NODES];
__device__ int   g_BSUM[SCAN_BLKS];
__device__ int   g_CSR[N_EDGES];

// ---------------- init: zero all stats + pool in one launch ----------------
__global__ void init_kernel(float* stats, float* pool) {
    int i = blockIdx.x * 256 + threadIdx.x;
    if (i < 3 * 2 * HID) stats[i] = 0.f;
    if (i < N_GRAPHS * HID) pool[i] = 0.f;
}
__global__ void zeroi_kernel(int* p, int n) {
    int i = blockIdx.x * blockDim.x + threadIdx.x;
    if (i < n) p[i] = 0;
}

// ================= CSR build =================
__global__ void hist_kernel(const int* __restrict__ ei, int* __restrict__ deg) {
    int e = blockIdx.x * blockDim.x + threadIdx.x;
    if (e < N_EDGES) atomicAdd(&deg[ei[N_EDGES + e]], 1);
}

__global__ void scan_block_kernel(const int* __restrict__ deg,
                                  int* __restrict__ offs, int* __restrict__ bsum) {
    __shared__ int s[256];
    int tid = threadIdx.x;
    int i = blockIdx.x * 256 + tid;
    int v = (i < N_NODES) ? deg[i] : 0;
    s[tid] = v;
    __syncthreads();
    #pragma unroll
    for (int d = 1; d < 256; d <<= 1) {
        int t = (tid >= d) ? s[tid - d] : 0;
        __syncthreads();
        s[tid] += t;
        __syncthreads();
    }
    if (i < N_NODES) offs[i] = s[tid] - v;
    if (tid == 255) bsum[blockIdx.x] = s[255];
}

__global__ void scan_bsum_kernel(int* __restrict__ bsum) {
    __shared__ int s[512];
    int tid = threadIdx.x;
    int v = (tid < SCAN_BLKS) ? bsum[tid] : 0;
    s[tid] = v;
    __syncthreads();
    #pragma unroll
    for (int d = 1; d < 512; d <<= 1) {
        int t = (tid >= d) ? s[tid - d] : 0;
        __syncthreads();
        s[tid] += t;
        __syncthreads();
    }
    if (tid < SCAN_BLKS) bsum[tid] = s[tid] - v;
}

__global__ void scan_add_kernel(int* __restrict__ offs, const int* __restrict__ bsum,
                                int* __restrict__ curs) {
    int i = blockIdx.x * 256 + threadIdx.x;
    if (i < N_NODES) {
        int o = offs[i] + bsum[blockIdx.x];
        offs[i] = o;
        curs[i] = o;
    }
}

__global__ void fill_kernel(const int* __restrict__ ei, int* __restrict__ curs,
                            int* __restrict__ csr) {
    int e = blockIdx.x * blockDim.x + threadIdx.x;
    if (e < N_EDGES) {
        int d = ei[N_EDGES + e];
        int slot = atomicAdd(&curs[d], 1);
        csr[slot] = ei[e];
    }
}

// ================= gather-aggregate (atomic-free, BN fused, 4-edge unroll) =================
__global__ __launch_bounds__(256)
void gather64_kernel(const int* __restrict__ deg, const int* __restrict__ offs,
                     const int* __restrict__ csr, const float* __restrict__ z,
                     float* __restrict__ outz) {
    int node = (blockIdx.x * 256 + threadIdx.x) >> 5;
    if (node >= N_NODES) return;
    int lane = threadIdx.x & 31;
    int c = lane * 2;
    float2 acc = *(const float2*)(z + (size_t)node * IN_C + c);
    int beg = offs[node], n = deg[node];
    int e = 0;
    for (; e + 4 <= n; e += 4) {
        int s0 = csr[beg + e],     s1 = csr[beg + e + 1];
        int s2 = csr[beg + e + 2], s3 = csr[beg + e + 3];
        float2 v0 = *(const float2*)(z + (size_t)s0 * IN_C + c);
        float2 v1 = *(const float2*)(z + (size_t)s1 * IN_C + c);
        float2 v2 = *(const float2*)(z + (size_t)s2 * IN_C + c);
        float2 v3 = *(const float2*)(z + (size_t)s3 * IN_C + c);
        acc.x += (v0.x + v1.x) + (v2.x + v3.x);
        acc.y += (v0.y + v1.y) + (v2.y + v3.y);
    }
    for (; e < n; e++) {
        int s0 = csr[beg + e];
        float2 v0 = *(const float2*)(z + (size_t)s0 * IN_C + c);
        acc.x += v0.x; acc.y += v0.y;
    }
    *(float2*)(outz + (size_t)node * IN_C + c) = acc;
}

__global__ __launch_bounds__(256)
void gather128_kernel(const int* __restrict__ deg, const int* __restrict__ offs,
                      const int* __restrict__ csr, const float* __restrict__ z,
                      const float* __restrict__ scale, const float* __restrict__ shift,
                      float* __restrict__ outz) {
    int node = (blockIdx.x * 256 + threadIdx.x) >> 5;
    if (node >= N_NODES) return;
    int lane = threadIdx.x & 31;
    int c = lane * 4;
    float4 sc = *(const float4*)(scale + c);
    float4 sh = *(const float4*)(shift + c);

    float4 v = *(const float4*)(z + (size_t)node * HID + c);
    float4 acc;
    acc.x = fmaxf(fmaf(v.x, sc.x, sh.x), 0.f);
    acc.y = fmaxf(fmaf(v.y, sc.y, sh.y), 0.f);
    acc.z = fmaxf(fmaf(v.z, sc.z, sh.z), 0.f);
    acc.w = fmaxf(fmaf(v.w, sc.w, sh.w), 0.f);

    int beg = offs[node], n = deg[node];
    int e = 0;
    for (; e + 4 <= n; e += 4) {
        int s0 = csr[beg + e],     s1 = csr[beg + e + 1];
        int s2 = csr[beg + e + 2], s3 = csr[beg + e + 3];
        float4 v0 = *(const float4*)(z + (size_t)s0 * HID + c);
        float4 v1 = *(const float4*)(z + (size_t)s1 * HID + c);
        float4 v2 = *(const float4*)(z + (size_t)s2 * HID + c);
        float4 v3 = *(const float4*)(z + (size_t)s3 * HID + c);
        acc.x += (fmaxf(fmaf(v0.x, sc.x, sh.x), 0.f) + fmaxf(fmaf(v1.x, sc.x, sh.x), 0.f))
               + (fmaxf(fmaf(v2.x, sc.x, sh.x), 0.f) + fmaxf(fmaf(v3.x, sc.x, sh.x), 0.f));
        acc.y += (fmaxf(fmaf(v0.y, sc.y, sh.y), 0.f) + fmaxf(fmaf(v1.y, sc.y, sh.y), 0.f))
               + (fmaxf(fmaf(v2.y, sc.y, sh.y), 0.f) + fmaxf(fmaf(v3.y, sc.y, sh.y), 0.f));
        acc.z += (fmaxf(fmaf(v0.z, sc.z, sh.z), 0.f) + fmaxf(fmaf(v1.z, sc.z, sh.z), 0.f))
               + (fmaxf(fmaf(v2.z, sc.z, sh.z), 0.f) + fmaxf(fmaf(v3.z, sc.z, sh.z), 0.f));
        acc.w += (fmaxf(fmaf(v0.w, sc.w, sh.w), 0.f) + fmaxf(fmaf(v1.w, sc.w, sh.w), 0.f))
               + (fmaxf(fmaf(v2.w, sc.w, sh.w), 0.f) + fmaxf(fmaf(v3.w, sc.w, sh.w), 0.f));
    }
    for (; e < n; e++) {
        int s0 = csr[beg + e];
        float4 v0 = *(const float4*)(z + (size_t)s0 * HID + c);
        acc.x += fmaxf(fmaf(v0.x, sc.x, sh.x), 0.f);
        acc.y += fmaxf(fmaf(v0.y, sc.y, sh.y), 0.f);
        acc.z += fmaxf(fmaf(v0.z, sc.z, sh.z), 0.f);
        acc.w += fmaxf(fmaf(v0.w, sc.w, sh.w), 0.f);
    }
    *(float4*)(outz + (size_t)node * HID + c) = acc;
}

// ---------------- fused MLP (tf32 mma.sync) — R11 champion form ----------------
template <int CIN>
__global__ __launch_bounds__(256, 2)
void mlp_kernel(const float* __restrict__ zin,
                const float* __restrict__ w1, const float* __restrict__ b1,
                const float* __restrict__ w2, const float* __restrict__ b2,
                float* __restrict__ zout, float* __restrict__ stats) {
    extern __shared__ float sm[];
    float* region = sm;                     // REGION_FL (z tile, then hidden tile)
    float* swp    = sm + REGION_FL;         // SW_FL (weight chunk, tf32 bits)
    float* ssum   = swp + SW_FL;            // HID
    float* ssq    = ssum + HID;             // HID

    const int SZS = CIN + 4;                // z row stride (A frags conflict-free)
    const int tid  = threadIdx.x;
    const int row0 = blockIdx.x * 128;
    const int lane = tid & 31;
    const int wid  = tid >> 5;
    const int g    = lane >> 2;
    const int tig  = lane & 3;
    const int wm   = (wid & 3) * 32;
    const int n0   = (wid >> 2) * 64;

    if (tid < HID) { ssum[tid] = 0.f; ssq[tid] = 0.f; }

    // ---- stage z tile as tf32 bits ----
    {
        const int QPR = CIN / 4;
        #pragma unroll
        for (int t = 0; t < (128 * QPR) / 256; t++) {
            int i = t * 256 + tid;
            int r = i / QPR, q = i % QPR;
            int gr = row0 + r;
            float4 v = make_float4(0.f, 0.f, 0.f, 0.f);
            if (gr < N_NODES)
                v = *(const float4*)(zin + (size_t)gr * CIN + q * 4);
            uint4 u = make_uint4(f2tf(v.x), f2tf(v.y), f2tf(v.z), f2tf(v.w));
            *(uint4*)&region[r * SZS + q * 4] = u;
        }
    }

    float acc[2][8][4];

    // ======== GEMM1 ========
    {
        #pragma unroll
        for (int mt = 0; mt < 2; mt++)
            #pragma unroll
            for (int j = 0; j < 8; j++) {
                int c = n0 + j * 8 + 2 * tig;
                acc[mt][j][0] = b1[c]; acc[mt][j][1] = b1[c + 1];
                acc[mt][j][2] = b1[c]; acc[mt][j][3] = b1[c + 1];
            }

        const int NKC = CIN / CK;
        for (int kc = 0; kc < NKC; kc++) {
            __syncthreads();
            #pragma unroll
            for (int t = 0; t < 4; t++) {
                int i = t * 256 + tid;
                int k = i >> 5, seg = i & 31;
                float4 v = *(const float4*)(w1 + (size_t)(kc * CK + k) * HID + seg * 4);
                uint4 u = make_uint4(f2tf(v.x), f2tf(v.y), f2tf(v.z), f2tf(v.w));
                *(uint4*)&swp[k * SWS + seg * 4] = u;
            }
            __syncthreads();
            const uint32_t* zr = (const uint32_t*)region;
            const uint32_t* wr = (const uint32_t*)swp;
            #pragma unroll
            for (int ks = 0; ks < CK / 8; ks++) {
                int kb = ks * 8;
                int kg = kc * CK + kb + tig;
                uint32_t a[2][4];
                #pragma unroll
                for (int mt = 0; mt < 2; mt++) {
                    int rb = wm + mt * 16 + g;
                    a[mt][0] = zr[rb * SZS + kg];
                    a[mt][1] = zr[(rb + 8) * SZS + kg];
                    a[mt][2] = zr[rb * SZS + kg + 4];
                    a[mt][3] = zr[(rb + 8) * SZS + kg + 4];
                }
                #pragma unroll
                for (int j = 0; j < 8; j++) {
                    int cB = n0 + j * 8 + g;
                    uint32_t b0 = wr[(kb + tig) * SWS + cB];
                    uint32_t bq = wr[(kb + tig + 4) * SWS + cB];
                    mma_tf32(acc[0][j], a[0], b0, bq);
                    mma_tf32(acc[1][j], a[1], b0, bq);
                }
            }
        }
        __syncthreads();

        #pragma unroll
        for (int mt = 0; mt < 2; mt++)
            #pragma unroll
            for (int half = 0; half < 2; half++) {
                int row = wm + mt * 16 + half * 8 + g;
                #pragma unroll
                for (int j = 0; j < 8; j++) {
                    int c = n0 + j * 8 + 2 * tig;
                    uint2 u = make_uint2(
                        f2tf(fmaxf(acc[mt][j][half * 2 + 0], 0.f)),
                        f2tf(fmaxf(acc[mt][j][half * 2 + 1], 0.f)));
                    *(uint2*)&region[row * 132 + c] = u;
                }
            }
    }

    // ======== GEMM2 ========
    {
        #pragma unroll
        for (int mt = 0; mt < 2; mt++)
            #pragma unroll
            for (int j = 0; j < 8; j++) {
                int c = n0 + j * 8 + 2 * tig;
                acc[mt][j][0] = b2[c]; acc[mt][j][1] = b2[c + 1];
                acc[mt][j][2] = b2[c]; acc[mt][j][3] = b2[c + 1];
            }

        for (int kc = 0; kc < HID / CK; kc++) {
            __syncthreads();
            #pragma unroll
            for (int t = 0; t < 4; t++) {
                int i = t * 256 + tid;
                int k = i >> 5, seg = i & 31;
                float4 v = *(const float4*)(w2 + (size_t)(kc * CK + k) * HID + seg * 4);
                uint4 u = make_uint4(f2tf(v.x), f2tf(v.y), f2tf(v.z), f2tf(v.w));
                *(uint4*)&swp[k * SWS + seg * 4] = u;
            }
            __syncthreads();
            const uint32_t* hr = (const uint32_t*)region;
            const uint32_t* wr = (const uint32_t*)swp;
            #pragma unroll
            for (int ks = 0; ks < CK / 8; ks++) {
                int kb = ks * 8;
                int kg = kc * CK + kb + tig;
                uint32_t a[2][4];
                #pragma unroll
                for (int mt = 0; mt < 2; mt++) {
                    int rb = wm + mt * 16 + g;
                    a[mt][0] = hr[rb * 132 + kg];
                    a[mt][1] = hr[(rb + 8) * 132 + kg];
                    a[mt][2] = hr[rb * 132 + kg + 4];
                    a[mt][3] = hr[(rb + 8) * 132 + kg + 4];
                }
                #pragma unroll
                for (int j = 0; j < 8; j++) {
                    int cB = n0 + j * 8 + g;
                    uint32_t b0 = wr[(kb + tig) * SWS + cB];
                    uint32_t bq = wr[(kb + tig + 4) * SWS + cB];
                    mma_tf32(acc[0][j], a[0], b0, bq);
                    mma_tf32(acc[1][j], a[1], b0, bq);
                }
            }
        }
    }

    // ======== epilogue ========
    float s[16], q[16];
    #pragma unroll
    for (int j = 0; j < 16; j++) { s[j] = 0.f; q[j] = 0.f; }

    #pragma unroll
    for (int mt = 0; mt < 2; mt++)
        #pragma unroll
        for (int half = 0; half < 2; half++) {
            int gr = row0 + wm + mt * 16 + half * 8 + g;
            if (gr < N_NODES) {
                #pragma unroll
                for (int j = 0; j < 8; j++) {
                    float v0 = acc[mt][j][half * 2 + 0];
                    float v1 = acc[mt][j][half * 2 + 1];
                    int c = n0 + j * 8 + 2 * tig;
                    *(float2*)&zout[(size_t)gr * HID + c] = make_float2(v0, v1);
                    s[2 * j] += v0;     q[2 * j] += v0 * v0;
                    s[2 * j + 1] += v1; q[2 * j + 1] += v1 * v1;
                }
            }
        }
    #pragma unroll
    for (int j = 0; j < 8; j++) {
        int c = n0 + j * 8 + 2 * tig;
        atomicAdd(&ssum[c], s[2 * j]);
        atomicAdd(&ssq[c], q[2 * j]);
        atomicAdd(&ssum[c + 1], s[2 * j + 1]);
        atomicAdd(&ssq[c + 1], q[2 * j + 1]);
    }
    __syncthreads();
    if (tid < HID) {
        atomicAdd(&stats[tid], ssum[tid]);
        atomicAdd(&stats[HID + tid], ssq[tid]);
    }
}

// ---------------- BN finalize ----------------
__global__ void bn_finalize_kernel(const float* __restrict__ gamma,
                                   const float* __restrict__ beta,
                                   const float* __restrict__ stats,
                                   float* __restrict__ scale,
                                   float* __restrict__ shift) {
    int c = threadIdx.x;
    float mean = stats[c] * (1.f / N_NODES);
    float var  = stats[HID + c] * (1.f / N_NODES) - mean * mean;
    float inv  = rsqrtf(var + BN_EPS);
    float sc   = gamma[c] * inv;
    scale[c] = sc;
    shift[c] = beta[c] - mean * sc;
}

// ---------------- mean pool with fused BN+relu (batch sorted) ----------------
__global__ void pool_kernel(const float* __restrict__ z, const int* __restrict__ batch,
                            const float* __restrict__ scale, const float* __restrict__ shift,
                            float* __restrict__ pool) {
    __shared__ int sb[256];
    int r0  = blockIdx.x * 256;
    int tid = threadIdx.x;  // 128 threads, one column each
    for (int i = tid; i < 256; i += 128) {
        int gr = r0 + i;
        sb[i] = (gr < N_NODES) ? batch[gr] : -1;
    }
    __syncthreads();
    int c = tid;
    float sc = scale[c], sh = shift[c];
    float sum = 0.f;
    int cur = sb[0];
    for (int i = 0; i < 256; i++) {
        int gr = r0 + i;
        if (gr >= N_NODES) break;
        int b = sb[i];
        if (b != cur) {
            atomicAdd(&pool[cur * HID + c], sum);
            sum = 0.f; cur = b;
        }
        sum += fmaxf(fmaf(z[(long long)gr * HID + c], sc, sh), 0.f);
    }
    if (cur >= 0) atomicAdd(&pool[cur * HID + c], sum);
}

// ---------------- per-graph counts via binary search ----------------
__global__ void count_kernel(const int* __restrict__ batch, float* __restrict__ cinv) {
    int g = threadIdx.x;
    int lo = 0, hi = N_NODES;
    while (lo < hi) { int m = (lo + hi) >> 1; if (batch[m] < g) lo = m + 1; else hi = m; }
    int a = lo;
    lo = 0; hi = N_NODES;
    while (lo < hi) { int m = (lo + hi) >> 1; if (batch[m] < g + 1) lo = m + 1; else hi = m; }
    float cnt = (float)(lo - a);
    cinv[g] = 1.f / fmaxf(cnt, 1.f);
}

// ---------------- final projection ----------------
__global__ void proj_kernel(const float* __restrict__ w, const float* __restrict__ b,
                            const float* __restrict__ pool, const float* __restrict__ cinv,
                            float* __restrict__ out) {
    __shared__ float hg[HID];
    int g = blockIdx.x, t = threadIdx.x;
    hg[t] = pool[g * HID + t] * cinv[g];
    __syncthreads();
    float acc = b[t];
    #pragma unroll 8
    for (int k = 0; k < HID; k++) acc = fmaf(hg[k], w[k * HID + t], acc);
    out[g * HID + t] = acc;
}

// ---------------- host orchestration ----------------
static void* sym(const void* s) {
    void* p = nullptr;
    cudaGetSymbolAddress(&p, s);
    return p;
}

extern "C" void kernel_launch(void* const* d_in, const int* in_sizes, int n_in,
                              void* d_out, int out_size) {
    const float* x     = (const float*)d_in[0];
    const int*   ei    = (const int*)d_in[1];
    const int*   batch = (const int*)d_in[2];
    const float* L[3][6];
    for (int l = 0; l < 3; l++)
        for (int k = 0; k < 6; k++) L[l][k] = (const float*)d_in[3 + 6 * l + k];
    const float* proj_w = (const float*)d_in[21];
    const float* proj_b = (const float*)d_in[22];
    float* out = (float*)d_out;

    float* Z0    = (float*)sym(g_Z0);
    float* Z1    = (float*)sym(g_Z1);
    float* AGG   = (float*)sym(g_AGG);
    float* STATS = (float*)sym(g_STATS);
    float* SCALE = (float*)sym(g_SCALE);
    float* SHIFT = (float*)sym(g_SHIFT);
    float* POOL  = (float*)sym(g_POOL);
    float* CINV  = (float*)sym(g_CINV);
    int*   DEG   = (int*)sym(g_DEG);
    int*   OFFS  = (int*)sym(g_OFFS);
    int*   CURS  = (int*)sym(g_CURS);
    int*   BSUM  = (int*)sym(g_BSUM);
    int*   CSR   = (int*)sym(g_CSR);

    const int smemMlp = (REGION_FL + SW_FL + 2 * HID) * 4;   // ~86 KB -> 2 CTAs/SM
    cudaFuncSetAttribute(mlp_kernel<IN_C>, cudaFuncAttributeMaxDynamicSharedMemorySize, smemMlp);
    cudaFuncSetAttribute(mlp_kernel<HID>,  cudaFuncAttributeMaxDynamicSharedMemorySize, smemMlp);

    const int mlpBlocks  = (N_NODES + 127) / 128;
    const int edgeBlocks = (N_EDGES + 255) / 256;
    const int gathBlocks = (N_NODES * 32 + 255) / 256;   // warp per node

    // ---- upfront: stats+pool zero, per-graph counts ----
    init_kernel<<<(N_GRAPHS * HID + 255) / 256, 256>>>(STATS, POOL);
    count_kernel<<<1, N_GRAPHS>>>(batch, CINV);

    // ---- CSR build (reused by all 3 layers) ----
    zeroi_kernel<<<SCAN_BLKS, 256>>>(DEG, N_NODES);
    hist_kernel<<<edgeBlocks, 256>>>(ei, DEG);
    scan_block_kernel<<<SCAN_BLKS, 256>>>(DEG, OFFS, BSUM);
    scan_bsum_kernel<<<1, 512>>>(BSUM);
    scan_add_kernel<<<SCAN_BLKS, 256>>>(OFFS, BSUM, CURS);
    fill_kernel<<<edgeBlocks, 256>>>(ei, CURS, CSR);

    // ---- layer 0 (CIN=64): z_in = x + sum_N x ----
    gather64_kernel<<<gathBlocks, 256>>>(DEG, OFFS, CSR, x, AGG);
    mlp_kernel<IN_C><<<mlpBlocks, 256, smemMlp>>>(
        AGG, L[0][0], L[0][1], L[0][2], L[0][3], Z0, STATS);
    bn_finalize_kernel<<<1, HID>>>(L[0][4], L[0][5], STATS, SCALE, SHIFT);

    // ---- layers 1,2 (CIN=128), BN of previous layer fused into gather ----
    const float* zprev = Z0;
    float* zcur = Z1;
    for (int l = 1; l < 3; l++) {
        const float* sc = SCALE + (l - 1) * HID;
        const float* sh = SHIFT + (l - 1) * HID;
        gather128_kernel<<<gathBlocks, 256>>>(DEG, OFFS, CSR, zprev, sc, sh, AGG);
        mlp_kernel<HID><<<mlpBlocks, 256, smemMlp>>>(
            AGG, L[l][0], L[l][1], L[l][2], L[l][3], zcur, STATS + l * 2 * HID);
        bn_finalize_kernel<<<1, HID>>>(L[l][4], L[l][5], STATS + l * 2 * HID,
                                       SCALE + l * HID, SHIFT + l * HID);
        const float* t = zprev; zprev = zcur; zcur = (float*)t;
    }

    // ---- pool + projection (BN of layer 2 fused into pool) ----
    pool_kernel<<<(N_NODES + 255) / 256, 128>>>(zprev, batch, SCALE + 2 * HID, SHIFT + 2 * HID, POOL);
    proj_kernel<<<N_GRAPHS, HID>>>(proj_w, proj_b, POOL, CINV, out);
}